// round 15
// baseline (speedup 1.0000x reference)
#include <cuda_runtime.h>
#include <cstdint>

#define MARGIN 0.2f
#define NEG_BIG (-3.0e38f)

// Scratch (device globals; no allocation allowed).
__device__ float g_s1[128 * 128];   // term-1 scores
__device__ float g_s2[128 * 128];   // TOTAL scores (term1 + term2)

// Preprocessed bf16 hi/lo planes: per row 64 words (128 elems as bf16x2).
// Rows: im 128*36=4608 | s 128*50=6400 | pred 128*25=3200 | crp 128*30=3840
__device__ uint32_t g_im_hi[4608 * 64],  g_im_lo[4608 * 64];
__device__ uint32_t g_s_hi [6400 * 64],  g_s_lo [6400 * 64];
__device__ uint32_t g_pr_hi[3200 * 64],  g_pr_lo[3200 * 64];
__device__ uint32_t g_cr_hi[3840 * 64],  g_cr_lo[3840 * 64];

__device__ __forceinline__ float bf16_hi(float a) {
    uint16_t u;
    asm("cvt.rn.bf16.f32 %0, %1;" : "=h"(u) : "f"(a));
    return __uint_as_float(((uint32_t)u) << 16);
}
__device__ __forceinline__ uint32_t pack_bf16x2(float a, float b) {
    uint32_t r;
    asm("cvt.rn.bf16x2.f32 %0, %1, %2;" : "=r"(r) : "f"(b), "f"(a));
    return r;
}

// m16n8k16 bf16 MMA, fp32 accumulate (sm_80+ path; compiles for base sm_103)
#define MMA_BF16(d, a, b) \
    asm volatile("mma.sync.aligned.m16n8k16.row.col.f32.bf16.bf16.f32 " \
        "{%0,%1,%2,%3}, {%4,%5,%6,%7}, {%8,%9}, {%0,%1,%2,%3};" \
        : "+f"((d)[0]), "+f"((d)[1]), "+f"((d)[2]), "+f"((d)[3]) \
        : "r"((a)[0]), "r"((a)[1]), "r"((a)[2]), "r"((a)[3]), \
          "r"((b)[0]), "r"((b)[1]))

// ---- Preprocess: fp32 -> hi/lo bf16x2 planes, all 4 tensors in one kernel.
static constexpr int NQ_IM = 4608 * 32;   // float4 count
static constexpr int NQ_S  = 6400 * 32;
static constexpr int NQ_PR = 3200 * 32;
static constexpr int NQ_CR = 3840 * 32;
static constexpr int NQ_TOTAL = NQ_IM + NQ_S + NQ_PR + NQ_CR;   // 577536

__global__ __launch_bounds__(256)
void preprocess(const float* __restrict__ im, const float* __restrict__ s,
                const float* __restrict__ pr, const float* __restrict__ cr)
{
    int idx = blockIdx.x * 256 + threadIdx.x;
    if (idx >= NQ_TOTAL) return;
    const float4* src;
    uint2 *hi, *lo;
    int local = idx;
    if (idx < NQ_IM) {
        src = (const float4*)im; hi = (uint2*)g_im_hi; lo = (uint2*)g_im_lo;
    } else if (idx < NQ_IM + NQ_S) {
        local -= NQ_IM;
        src = (const float4*)s;  hi = (uint2*)g_s_hi;  lo = (uint2*)g_s_lo;
    } else if (idx < NQ_IM + NQ_S + NQ_PR) {
        local -= NQ_IM + NQ_S;
        src = (const float4*)pr; hi = (uint2*)g_pr_hi; lo = (uint2*)g_pr_lo;
    } else {
        local -= NQ_IM + NQ_S + NQ_PR;
        src = (const float4*)cr; hi = (uint2*)g_cr_hi; lo = (uint2*)g_cr_lo;
    }
    float4 v = src[local];
    float hx = bf16_hi(v.x), hy = bf16_hi(v.y);
    float hz = bf16_hi(v.z), hw = bf16_hi(v.w);
    uint2 hwd, lwd;
    hwd.x = (__float_as_uint(hy) & 0xFFFF0000u) | (__float_as_uint(hx) >> 16);
    hwd.y = (__float_as_uint(hw) & 0xFFFF0000u) | (__float_as_uint(hz) >> 16);
    lwd.x = pack_bf16x2(v.x - hx, v.y - hy);
    lwd.y = pack_bf16x2(v.z - hz, v.w - hw);
    hi[local] = hwd;
    lo[local] = lwd;
}

// ---- SMEM: K chunked by 64 (32 words/row). Row stride 36 words
// (36 mod 32 == 4) -> fragment LDS bank = 4*gr + tc covers all 32 banks.
static constexpr int KC = 64;                       // K chunk (elements)
static constexpr int SW = 36;                       // row stride (words)
static constexpr int OFF_A_HI = 0;                  // 128*36*4 = 18432 B
static constexpr int OFF_A_LO = 18432;
static constexpr int OFF_B_HI = 36864;
static constexpr int OFF_B_LO = 55296;
static constexpr int SMEM_TOTAL = 73728;            // 72 KB -> 2 CTAs/SM
static constexpr int SD = 131;  // epilogue Dcol stride: odd -> conflict-free reads

// ---------------------------------------------------------------------------
// score_tc<O, W, NIMG, NCAP, CSLOT, SLOT>
// CTA: M=128 rows = NIMG images x O objects (zero-padded),
//      N=128 cols = NCAP captions x CSLOT word slots (zero-padded).
// Operands pre-split to bf16 hi/lo planes; staging is pure uint4 copy.
// 3-pass bf16 split: D = Ahi*Bhi + Ahi*Blo + Alo*Bhi.
// ---------------------------------------------------------------------------
template<int O, int W, int NIMG, int NCAP, int CSLOT, int SLOT>
__global__ __launch_bounds__(256, 2)
void score_tc(const uint32_t* __restrict__ Ahi_g,
              const uint32_t* __restrict__ Alo_g,
              const uint32_t* __restrict__ Bhi_g,
              const uint32_t* __restrict__ Blo_g,
              const int* __restrict__ img_l,
              const int* __restrict__ cap_l,
              int B)
{
    extern __shared__ char smem[];
    uint32_t* Ah = reinterpret_cast<uint32_t*>(smem + OFF_A_HI);
    uint32_t* Al = reinterpret_cast<uint32_t*>(smem + OFF_A_LO);
    uint32_t* Bh = reinterpret_cast<uint32_t*>(smem + OFF_B_HI);
    uint32_t* Bl = reinterpret_cast<uint32_t*>(smem + OFF_B_LO);

    const int tid  = threadIdx.x;
    const int wid  = tid >> 5;
    const int lane = tid & 31;
    const int gr   = lane >> 2;
    const int tc   = lane & 3;

    const int gi = blockIdx.y;
    const int cg = blockIdx.x;
    const int ng = min(NIMG, B - gi * NIMG);
    const int arows = ng * O;
    const int gbase = gi * NIMG * O;            // global A row base

    const int wm = wid & 3, wn = wid >> 2;
    const int m0 = wm * 32, n0 = wn * 64;

    float acc[2][8][4];
    #pragma unroll
    for (int ms = 0; ms < 2; ms++)
        #pragma unroll
        for (int ns = 0; ns < 8; ns++)
            #pragma unroll
            for (int j = 0; j < 4; j++) acc[ms][ns][j] = 0.0f;

    const uint4* Ahi4 = reinterpret_cast<const uint4*>(Ahi_g);
    const uint4* Alo4 = reinterpret_cast<const uint4*>(Alo_g);
    const uint4* Bhi4 = reinterpret_cast<const uint4*>(Bhi_g);
    const uint4* Blo4 = reinterpret_cast<const uint4*>(Blo_g);
    const uint4 zero4 = make_uint4(0u, 0u, 0u, 0u);

    #pragma unroll 1
    for (int chunk = 0; chunk < 2; chunk++) {
        __syncthreads();   // previous chunk consumed

        // ---- Stage A chunk: pure copy (row = 8 uint4 of 32 words) ----
        #pragma unroll
        for (int u = tid; u < 128 * 8; u += 256) {
            int r = u >> 3, q = u & 7;
            uint4 h = zero4, l = zero4;
            if (r < arows) {
                int gidx = (gbase + r) * 16 + chunk * 8 + q;
                h = Ahi4[gidx]; l = Alo4[gidx];
            }
            int wi = r * SW + q * 4;
            *reinterpret_cast<uint4*>(Ah + wi) = h;
            *reinterpret_cast<uint4*>(Al + wi) = l;
        }
        // ---- Stage B chunk: slot-padded copy ----
        #pragma unroll
        for (int u = tid; u < 128 * 8; u += 256) {
            int n = u >> 3, q = u & 7;
            int ci = n / CSLOT, w = n % CSLOT;
            uint4 h = zero4, l = zero4;
            if (w < W) {
                int gidx = ((cg * NCAP + ci) * W + w) * 16 + chunk * 8 + q;
                h = Bhi4[gidx]; l = Blo4[gidx];
            }
            int wi = n * SW + q * 4;
            *reinterpret_cast<uint4*>(Bh + wi) = h;
            *reinterpret_cast<uint4*>(Bl + wi) = l;
        }
        __syncthreads();

        // ---- 4 k-steps of 16 per chunk ----
        #pragma unroll
        for (int kk = 0; kk < KC / 2; kk += 8) {
            uint32_t ah[2][4], al[2][4];
            #pragma unroll
            for (int ms = 0; ms < 2; ms++) {
                int r = m0 + ms * 16 + gr;
                ah[ms][0] = Ah[r * SW + kk + tc];
                ah[ms][1] = Ah[(r + 8) * SW + kk + tc];
                ah[ms][2] = Ah[r * SW + kk + tc + 4];
                ah[ms][3] = Ah[(r + 8) * SW + kk + tc + 4];
                al[ms][0] = Al[r * SW + kk + tc];
                al[ms][1] = Al[(r + 8) * SW + kk + tc];
                al[ms][2] = Al[r * SW + kk + tc + 4];
                al[ms][3] = Al[(r + 8) * SW + kk + tc + 4];
            }
            uint32_t bh[8][2], bl[8][2];
            #pragma unroll
            for (int ns = 0; ns < 8; ns++) {
                int n = n0 + ns * 8 + gr;
                bh[ns][0] = Bh[n * SW + kk + tc];
                bh[ns][1] = Bh[n * SW + kk + tc + 4];
                bl[ns][0] = Bl[n * SW + kk + tc];
                bl[ns][1] = Bl[n * SW + kk + tc + 4];
            }
            #pragma unroll
            for (int ms = 0; ms < 2; ms++)
                #pragma unroll
                for (int ns = 0; ns < 8; ns++) {
                    MMA_BF16(acc[ms][ns], ah[ms], bh[ns]);
                    MMA_BF16(acc[ms][ns], ah[ms], bl[ns]);
                    MMA_BF16(acc[ms][ns], al[ms], bh[ns]);
                }
        }
    }
    __syncthreads();   // MMAs done; whole smem reusable

    // ---- D (regs) -> SMEM col-major [col][row], stride SD=131 ----
    float* Dcol = reinterpret_cast<float*>(smem);           // 128*131*4 = 67072 B
    float* pooled = reinterpret_cast<float*>(smem + 67072); // NIMG*128 floats
    #pragma unroll
    for (int ms = 0; ms < 2; ms++) {
        int r = m0 + ms * 16 + gr;
        #pragma unroll
        for (int ns = 0; ns < 8; ns++) {
            int c = n0 + ns * 8 + 2 * tc;
            Dcol[c * SD + r]           = acc[ms][ns][0];
            Dcol[(c + 1) * SD + r]     = acc[ms][ns][1];
            Dcol[c * SD + r + 8]       = acc[ms][ns][2];
            Dcol[(c + 1) * SD + r + 8] = acc[ms][ns][3];
        }
    }
    __syncthreads();

    // ---- Masked max over objects per (image, col); stride-131 reads are
    // conflict-free across consecutive-c lanes ----
    for (int u = tid; u < NIMG * 128; u += 256) {
        int j = u >> 7, c = u & 127;
        int lim = (j < ng) ? img_l[gi * NIMG + j] : 0;
        float m = NEG_BIG;
        const float* col = Dcol + c * SD + j * O;
        for (int r = 0; r < lim; r++) m = fmaxf(m, col[r]);
        pooled[u] = m;
    }
    __syncthreads();

    // ---- Per-(image, caption) word sums -> global scores ----
    if (tid < NIMG * NCAP) {
        int j = tid / NCAP, ci = tid % NCAP;
        if (j < ng) {
            float s = 0.0f;
            #pragma unroll
            for (int w = 0; w < W; w++) s += pooled[j * 128 + ci * CSLOT + w];
            int i = gi * NIMG + j, c = cg * NCAP + ci;
            float r = s / (float)cap_l[c];
            if (SLOT == 0) g_s1[i * B + c] = r;
            else           g_s2[i * B + c] = g_s1[i * B + c] + r;
        }
    }
}

// ---------------------------------------------------------------------------
// Hinge loss over B x B total scores (g_s2). Deterministic.
// ---------------------------------------------------------------------------
__global__ void loss_kernel(float* __restrict__ out, int B)
{
    __shared__ float red[128];
    const int t = threadIdx.x;
    const float dt = g_s2[t * B + t];
    float m1 = 0.0f, m2 = 0.0f;
    for (int k = 0; k < B; k++) {
        if (k == t) continue;
        m1 = fmaxf(m1, MARGIN + g_s2[t * B + k] - dt);
        m2 = fmaxf(m2, MARGIN + g_s2[k * B + t] - dt);
    }
    red[t] = m1 + m2;
    __syncthreads();
    for (int s = 64; s > 0; s >>= 1) {
        if (t < s && t + s < B) red[t] += red[t + s];
        __syncthreads();
    }
    if (t == 0) out[0] = red[0];
}

// ---------------------------------------------------------------------------
// Inputs (metadata order):
//  0 im (B,36,128) f32 | 1 im_l (B) i32 | 2 s (B,50,128) f32 | 3 s_l (B) i32
//  4 pred (B,25,128)   | 5 pred_l       | 6/7 unused | 8 c_r_pred (B,30,128) | 9 c_r_l
// Output: scalar f32.
// ---------------------------------------------------------------------------
extern "C" void kernel_launch(void* const* d_in, const int* in_sizes, int n_in,
                              void* d_out, int out_size)
{
    const float* im     = (const float*)d_in[0];
    const int*   im_l   = (const int*)  d_in[1];
    const float* s      = (const float*)d_in[2];
    const int*   s_l    = (const int*)  d_in[3];
    const float* pred   = (const float*)d_in[4];
    const int*   pred_l = (const int*)  d_in[5];
    const float* crp    = (const float*)d_in[8];
    const int*   crl    = (const int*)  d_in[9];

    const int B = in_sizes[1];   // 128

    static uint32_t *p_im_hi = nullptr, *p_im_lo, *p_s_hi, *p_s_lo,
                    *p_pr_hi, *p_pr_lo, *p_cr_hi, *p_cr_lo;
    if (!p_im_hi) {
        cudaGetSymbolAddress((void**)&p_im_hi, g_im_hi);
        cudaGetSymbolAddress((void**)&p_im_lo, g_im_lo);
        cudaGetSymbolAddress((void**)&p_s_hi,  g_s_hi);
        cudaGetSymbolAddress((void**)&p_s_lo,  g_s_lo);
        cudaGetSymbolAddress((void**)&p_pr_hi, g_pr_hi);
        cudaGetSymbolAddress((void**)&p_pr_lo, g_pr_lo);
        cudaGetSymbolAddress((void**)&p_cr_hi, g_cr_hi);
        cudaGetSymbolAddress((void**)&p_cr_lo, g_cr_lo);
        cudaFuncSetAttribute(score_tc<36, 50, 3, 2, 64, 0>,
                             cudaFuncAttributeMaxDynamicSharedMemorySize, SMEM_TOTAL);
        cudaFuncSetAttribute(score_tc<25, 30, 5, 4, 32, 1>,
                             cudaFuncAttributeMaxDynamicSharedMemorySize, SMEM_TOTAL);
    }

    preprocess<<<(NQ_TOTAL + 255) / 256, 256>>>(im, s, pred, crp);

    // Term 1: 3 images x 2 captions per CTA -> grid (64, 43)
    score_tc<36, 50, 3, 2, 64, 0><<<dim3(B / 2, (B + 2) / 3), 256, SMEM_TOTAL>>>(
        p_im_hi, p_im_lo, p_s_hi, p_s_lo, im_l, s_l, B);

    // Term 2: 5 images x 4 captions per CTA -> grid (32, 26)
    score_tc<25, 30, 5, 4, 32, 1><<<dim3(B / 4, (B + 4) / 5), 256, SMEM_TOTAL>>>(
        p_pr_hi, p_pr_lo, p_cr_hi, p_cr_lo, pred_l, crl, B);

    loss_kernel<<<1, 128>>>((float*)d_out, B);
}

// round 16
// speedup vs baseline: 1.0103x; 1.0103x over previous
#include <cuda_runtime.h>
#include <cstdint>

#define MARGIN 0.2f
#define NEG_BIG (-3.0e38f)

// Scratch (device globals; no allocation allowed).
__device__ float g_s1[128 * 128];   // term-1 scores
__device__ float g_s2[128 * 128];   // term-2 scores (independent of g_s1 now)

// Preprocessed bf16 hi/lo planes: per row 64 words (128 elems as bf16x2).
// Rows: im 128*36=4608 | s 128*50=6400 | pred 128*25=3200 | crp 128*30=3840
__device__ uint32_t g_im_hi[4608 * 64],  g_im_lo[4608 * 64];
__device__ uint32_t g_s_hi [6400 * 64],  g_s_lo [6400 * 64];
__device__ uint32_t g_pr_hi[3200 * 64],  g_pr_lo[3200 * 64];
__device__ uint32_t g_cr_hi[3840 * 64],  g_cr_lo[3840 * 64];

__device__ __forceinline__ float bf16_hi(float a) {
    uint16_t u;
    asm("cvt.rn.bf16.f32 %0, %1;" : "=h"(u) : "f"(a));
    return __uint_as_float(((uint32_t)u) << 16);
}
__device__ __forceinline__ uint32_t pack_bf16x2(float a, float b) {
    uint32_t r;
    asm("cvt.rn.bf16x2.f32 %0, %1, %2;" : "=r"(r) : "f"(b), "f"(a));
    return r;
}

// m16n8k16 bf16 MMA, fp32 accumulate (sm_80+ path; compiles for base sm_103)
#define MMA_BF16(d, a, b) \
    asm volatile("mma.sync.aligned.m16n8k16.row.col.f32.bf16.bf16.f32 " \
        "{%0,%1,%2,%3}, {%4,%5,%6,%7}, {%8,%9}, {%0,%1,%2,%3};" \
        : "+f"((d)[0]), "+f"((d)[1]), "+f"((d)[2]), "+f"((d)[3]) \
        : "r"((a)[0]), "r"((a)[1]), "r"((a)[2]), "r"((a)[3]), \
          "r"((b)[0]), "r"((b)[1]))

// ---- Preprocess: fp32 -> hi/lo bf16x2 planes, all 4 tensors in one kernel.
static constexpr int NQ_IM = 4608 * 32;   // float4 count
static constexpr int NQ_S  = 6400 * 32;
static constexpr int NQ_PR = 3200 * 32;
static constexpr int NQ_CR = 3840 * 32;
static constexpr int NQ_TOTAL = NQ_IM + NQ_S + NQ_PR + NQ_CR;   // 577536

__global__ __launch_bounds__(256)
void preprocess(const float* __restrict__ im, const float* __restrict__ s,
                const float* __restrict__ pr, const float* __restrict__ cr)
{
    int idx = blockIdx.x * 256 + threadIdx.x;
    if (idx >= NQ_TOTAL) return;
    const float4* src;
    uint2 *hi, *lo;
    int local = idx;
    if (idx < NQ_IM) {
        src = (const float4*)im; hi = (uint2*)g_im_hi; lo = (uint2*)g_im_lo;
    } else if (idx < NQ_IM + NQ_S) {
        local -= NQ_IM;
        src = (const float4*)s;  hi = (uint2*)g_s_hi;  lo = (uint2*)g_s_lo;
    } else if (idx < NQ_IM + NQ_S + NQ_PR) {
        local -= NQ_IM + NQ_S;
        src = (const float4*)pr; hi = (uint2*)g_pr_hi; lo = (uint2*)g_pr_lo;
    } else {
        local -= NQ_IM + NQ_S + NQ_PR;
        src = (const float4*)cr; hi = (uint2*)g_cr_hi; lo = (uint2*)g_cr_lo;
    }
    float4 v = src[local];
    float hx = bf16_hi(v.x), hy = bf16_hi(v.y);
    float hz = bf16_hi(v.z), hw = bf16_hi(v.w);
    uint2 hwd, lwd;
    hwd.x = (__float_as_uint(hy) & 0xFFFF0000u) | (__float_as_uint(hx) >> 16);
    hwd.y = (__float_as_uint(hw) & 0xFFFF0000u) | (__float_as_uint(hz) >> 16);
    lwd.x = pack_bf16x2(v.x - hx, v.y - hy);
    lwd.y = pack_bf16x2(v.z - hz, v.w - hw);
    hi[local] = hwd;
    lo[local] = lwd;
}

// ---- SMEM: K chunked by 64 (32 words/row). Row stride 36 words
// (36 mod 32 == 4) -> fragment LDS bank = 4*gr + tc covers all 32 banks.
static constexpr int KC = 64;                       // K chunk (elements)
static constexpr int SW = 36;                       // row stride (words)
static constexpr int OFF_A_HI = 0;                  // 128*36*4 = 18432 B
static constexpr int OFF_A_LO = 18432;
static constexpr int OFF_B_HI = 36864;
static constexpr int OFF_B_LO = 55296;
static constexpr int SMEM_TOTAL = 73728;            // 72 KB -> 2 CTAs/SM
static constexpr int SD = 131;  // epilogue Dcol stride: odd -> conflict-free reads

// ---------------------------------------------------------------------------
// score_body<O, W, NIMG, NCAP, CSLOT, SLOT>  (device inline)
// CTA: M=128 rows = NIMG images x O objects (zero-padded),
//      N=128 cols = NCAP captions x CSLOT word slots (zero-padded).
// Operands pre-split to bf16 hi/lo planes; staging is pure uint4 copy.
// 3-pass bf16 split: D = Ahi*Bhi + Ahi*Blo + Alo*Bhi.
// ---------------------------------------------------------------------------
template<int O, int W, int NIMG, int NCAP, int CSLOT, int SLOT>
__device__ __forceinline__
void score_body(char* smem, int gi, int cg,
                const uint32_t* __restrict__ Ahi_g,
                const uint32_t* __restrict__ Alo_g,
                const uint32_t* __restrict__ Bhi_g,
                const uint32_t* __restrict__ Blo_g,
                const int* __restrict__ img_l,
                const int* __restrict__ cap_l,
                int B)
{
    uint32_t* Ah = reinterpret_cast<uint32_t*>(smem + OFF_A_HI);
    uint32_t* Al = reinterpret_cast<uint32_t*>(smem + OFF_A_LO);
    uint32_t* Bh = reinterpret_cast<uint32_t*>(smem + OFF_B_HI);
    uint32_t* Bl = reinterpret_cast<uint32_t*>(smem + OFF_B_LO);

    const int tid  = threadIdx.x;
    const int wid  = tid >> 5;
    const int lane = tid & 31;
    const int gr   = lane >> 2;
    const int tc   = lane & 3;

    const int ng = min(NIMG, B - gi * NIMG);
    const int arows = ng * O;
    const int gbase = gi * NIMG * O;            // global A row base

    const int wm = wid & 3, wn = wid >> 2;
    const int m0 = wm * 32, n0 = wn * 64;

    float acc[2][8][4];
    #pragma unroll
    for (int ms = 0; ms < 2; ms++)
        #pragma unroll
        for (int ns = 0; ns < 8; ns++)
            #pragma unroll
            for (int j = 0; j < 4; j++) acc[ms][ns][j] = 0.0f;

    const uint4* Ahi4 = reinterpret_cast<const uint4*>(Ahi_g);
    const uint4* Alo4 = reinterpret_cast<const uint4*>(Alo_g);
    const uint4* Bhi4 = reinterpret_cast<const uint4*>(Bhi_g);
    const uint4* Blo4 = reinterpret_cast<const uint4*>(Blo_g);
    const uint4 zero4 = make_uint4(0u, 0u, 0u, 0u);

    #pragma unroll 1
    for (int chunk = 0; chunk < 2; chunk++) {
        __syncthreads();   // previous chunk consumed

        // ---- Stage A chunk: pure copy (row = 8 uint4 of 32 words) ----
        #pragma unroll
        for (int u = tid; u < 128 * 8; u += 256) {
            int r = u >> 3, q = u & 7;
            uint4 h = zero4, l = zero4;
            if (r < arows) {
                int gidx = (gbase + r) * 16 + chunk * 8 + q;
                h = Ahi4[gidx]; l = Alo4[gidx];
            }
            int wi = r * SW + q * 4;
            *reinterpret_cast<uint4*>(Ah + wi) = h;
            *reinterpret_cast<uint4*>(Al + wi) = l;
        }
        // ---- Stage B chunk: slot-padded copy ----
        #pragma unroll
        for (int u = tid; u < 128 * 8; u += 256) {
            int n = u >> 3, q = u & 7;
            int ci = n / CSLOT, w = n % CSLOT;
            uint4 h = zero4, l = zero4;
            if (w < W) {
                int gidx = ((cg * NCAP + ci) * W + w) * 16 + chunk * 8 + q;
                h = Bhi4[gidx]; l = Blo4[gidx];
            }
            int wi = n * SW + q * 4;
            *reinterpret_cast<uint4*>(Bh + wi) = h;
            *reinterpret_cast<uint4*>(Bl + wi) = l;
        }
        __syncthreads();

        // ---- 4 k-steps of 16 per chunk ----
        #pragma unroll
        for (int kk = 0; kk < KC / 2; kk += 8) {
            uint32_t ah[2][4], al[2][4];
            #pragma unroll
            for (int ms = 0; ms < 2; ms++) {
                int r = m0 + ms * 16 + gr;
                ah[ms][0] = Ah[r * SW + kk + tc];
                ah[ms][1] = Ah[(r + 8) * SW + kk + tc];
                ah[ms][2] = Ah[r * SW + kk + tc + 4];
                ah[ms][3] = Ah[(r + 8) * SW + kk + tc + 4];
                al[ms][0] = Al[r * SW + kk + tc];
                al[ms][1] = Al[(r + 8) * SW + kk + tc];
                al[ms][2] = Al[r * SW + kk + tc + 4];
                al[ms][3] = Al[(r + 8) * SW + kk + tc + 4];
            }
            uint32_t bh[8][2], bl[8][2];
            #pragma unroll
            for (int ns = 0; ns < 8; ns++) {
                int n = n0 + ns * 8 + gr;
                bh[ns][0] = Bh[n * SW + kk + tc];
                bh[ns][1] = Bh[n * SW + kk + tc + 4];
                bl[ns][0] = Bl[n * SW + kk + tc];
                bl[ns][1] = Bl[n * SW + kk + tc + 4];
            }
            #pragma unroll
            for (int ms = 0; ms < 2; ms++)
                #pragma unroll
                for (int ns = 0; ns < 8; ns++) {
                    MMA_BF16(acc[ms][ns], ah[ms], bh[ns]);
                    MMA_BF16(acc[ms][ns], ah[ms], bl[ns]);
                    MMA_BF16(acc[ms][ns], al[ms], bh[ns]);
                }
        }
    }
    __syncthreads();   // MMAs done; whole smem reusable

    // ---- D (regs) -> SMEM col-major [col][row], stride SD=131 ----
    float* Dcol = reinterpret_cast<float*>(smem);           // 128*131*4 = 67072 B
    float* pooled = reinterpret_cast<float*>(smem + 67072); // NIMG*128 floats
    #pragma unroll
    for (int ms = 0; ms < 2; ms++) {
        int r = m0 + ms * 16 + gr;
        #pragma unroll
        for (int ns = 0; ns < 8; ns++) {
            int c = n0 + ns * 8 + 2 * tc;
            Dcol[c * SD + r]           = acc[ms][ns][0];
            Dcol[(c + 1) * SD + r]     = acc[ms][ns][1];
            Dcol[c * SD + r + 8]       = acc[ms][ns][2];
            Dcol[(c + 1) * SD + r + 8] = acc[ms][ns][3];
        }
    }
    __syncthreads();

    // ---- Masked max over objects per (image, col) ----
    for (int u = tid; u < NIMG * 128; u += 256) {
        int j = u >> 7, c = u & 127;
        int lim = (j < ng) ? img_l[gi * NIMG + j] : 0;
        float m = NEG_BIG;
        const float* col = Dcol + c * SD + j * O;
        for (int r = 0; r < lim; r++) m = fmaxf(m, col[r]);
        pooled[u] = m;
    }
    __syncthreads();

    // ---- Per-(image, caption) word sums -> global scores ----
    if (tid < NIMG * NCAP) {
        int j = tid / NCAP, ci = tid % NCAP;
        if (j < ng) {
            float s = 0.0f;
            #pragma unroll
            for (int w = 0; w < W; w++) s += pooled[j * 128 + ci * CSLOT + w];
            int i = gi * NIMG + j, c = cg * NCAP + ci;
            float r = s / (float)cap_l[c];
            if (SLOT == 0) g_s1[i * B + c] = r;
            else           g_s2[i * B + c] = r;   // independent of g_s1
        }
    }
}

// Grid split: term1 = 64 x 43 = 2752 CTAs, term2 = 32 x 26 = 832 CTAs.
static constexpr int G1 = 64 * 43;
static constexpr int G2 = 32 * 26;

__global__ __launch_bounds__(256, 2)
void score_fused(const uint32_t* __restrict__ im_hi, const uint32_t* __restrict__ im_lo,
                 const uint32_t* __restrict__ s_hi,  const uint32_t* __restrict__ s_lo,
                 const uint32_t* __restrict__ pr_hi, const uint32_t* __restrict__ pr_lo,
                 const uint32_t* __restrict__ cr_hi, const uint32_t* __restrict__ cr_lo,
                 const int* __restrict__ im_l, const int* __restrict__ s_l,
                 const int* __restrict__ pr_l, const int* __restrict__ cr_l,
                 int B)
{
    extern __shared__ char smem[];
    const int bid = blockIdx.x;
    if (bid < G1) {
        score_body<36, 50, 3, 2, 64, 0>(smem, bid / 64, bid % 64,
                                        im_hi, im_lo, s_hi, s_lo, im_l, s_l, B);
    } else {
        const int b2 = bid - G1;
        score_body<25, 30, 5, 4, 32, 1>(smem, b2 / 32, b2 % 32,
                                        pr_hi, pr_lo, cr_hi, cr_lo, pr_l, cr_l, B);
    }
}

// ---------------------------------------------------------------------------
// Hinge loss over B x B total scores (g_s1 + g_s2), SMEM-staged.
// 1024 threads: 8 threads per row; deterministic fixed-order ops.
// ---------------------------------------------------------------------------
static constexpr int LS = 129;                     // S row stride (words)
static constexpr int LOSS_SMEM = 128 * LS * 4;     // 66048 B

__global__ __launch_bounds__(1024)
void loss_kernel(float* __restrict__ out, int B)
{
    extern __shared__ float S[];
    __shared__ float red[128];
    const int tid = threadIdx.x;

    // Stage total-score matrix (coalesced global reads).
    for (int u = tid; u < 128 * 128; u += 1024) {
        int r = u >> 7, c = u & 127;
        S[r * LS + c] = g_s1[u] + g_s2[u];
    }
    __syncthreads();

    const int row  = tid >> 3;
    const int part = tid & 7;
    const float dt = S[row * LS + row];

    float m1 = 0.0f, m2 = 0.0f;
    #pragma unroll
    for (int i = 0; i < 16; i++) {
        int k = part + 8 * i;
        if (k != row) {
            m1 = fmaxf(m1, MARGIN + S[row * LS + k] - dt);
            m2 = fmaxf(m2, MARGIN + S[k * LS + row] - dt);
        }
    }
    // Reduce across the 8 parts of this row (contiguous lanes, width 8).
    #pragma unroll
    for (int s = 4; s > 0; s >>= 1) {
        m1 = fmaxf(m1, __shfl_down_sync(0xffffffffu, m1, s, 8));
        m2 = fmaxf(m2, __shfl_down_sync(0xffffffffu, m2, s, 8));
    }
    if (part == 0) red[row] = m1 + m2;
    __syncthreads();

    if (tid < 64) red[tid] += red[tid + 64];
    __syncthreads();
    if (tid < 32) {
        float v = red[tid] + red[tid + 32];
        #pragma unroll
        for (int s = 16; s > 0; s >>= 1)
            v += __shfl_down_sync(0xffffffffu, v, s);
        if (tid == 0) out[0] = v;
    }
}

// ---------------------------------------------------------------------------
// Inputs (metadata order):
//  0 im (B,36,128) f32 | 1 im_l (B) i32 | 2 s (B,50,128) f32 | 3 s_l (B) i32
//  4 pred (B,25,128)   | 5 pred_l       | 6/7 unused | 8 c_r_pred (B,30,128) | 9 c_r_l
// Output: scalar f32.
// ---------------------------------------------------------------------------
extern "C" void kernel_launch(void* const* d_in, const int* in_sizes, int n_in,
                              void* d_out, int out_size)
{
    const float* im     = (const float*)d_in[0];
    const int*   im_l   = (const int*)  d_in[1];
    const float* s      = (const float*)d_in[2];
    const int*   s_l    = (const int*)  d_in[3];
    const float* pred   = (const float*)d_in[4];
    const int*   pred_l = (const int*)  d_in[5];
    const float* crp    = (const float*)d_in[8];
    const int*   crl    = (const int*)  d_in[9];

    const int B = in_sizes[1];   // 128

    static uint32_t *p_im_hi = nullptr, *p_im_lo, *p_s_hi, *p_s_lo,
                    *p_pr_hi, *p_pr_lo, *p_cr_hi, *p_cr_lo;
    if (!p_im_hi) {
        cudaGetSymbolAddress((void**)&p_im_hi, g_im_hi);
        cudaGetSymbolAddress((void**)&p_im_lo, g_im_lo);
        cudaGetSymbolAddress((void**)&p_s_hi,  g_s_hi);
        cudaGetSymbolAddress((void**)&p_s_lo,  g_s_lo);
        cudaGetSymbolAddress((void**)&p_pr_hi, g_pr_hi);
        cudaGetSymbolAddress((void**)&p_pr_lo, g_pr_lo);
        cudaGetSymbolAddress((void**)&p_cr_hi, g_cr_hi);
        cudaGetSymbolAddress((void**)&p_cr_lo, g_cr_lo);
        cudaFuncSetAttribute(score_fused,
                             cudaFuncAttributeMaxDynamicSharedMemorySize, SMEM_TOTAL);
        cudaFuncSetAttribute(loss_kernel,
                             cudaFuncAttributeMaxDynamicSharedMemorySize, LOSS_SMEM);
    }

    preprocess<<<(NQ_TOTAL + 255) / 256, 256>>>(im, s, pred, crp);

    score_fused<<<G1 + G2, 256, SMEM_TOTAL>>>(
        p_im_hi, p_im_lo, p_s_hi, p_s_lo,
        p_pr_hi, p_pr_lo, p_cr_hi, p_cr_lo,
        im_l, s_l, pred_l, crl, B);

    loss_kernel<<<1, 1024, LOSS_SMEM>>>((float*)d_out, B);
}

// round 17
// speedup vs baseline: 1.0996x; 1.0884x over previous
#include <cuda_runtime.h>
#include <cstdint>

#define MARGIN 0.2f
#define NEG_BIG (-3.0e38f)

// Scratch (device globals; no allocation allowed).
__device__ float g_s1[128 * 128];   // term-1 scores
__device__ float g_s2[128 * 128];   // term-2 scores

// Preprocessed bf16 hi/lo planes: per row 64 words (128 elems as bf16x2).
// Rows: im 128*36=4608 | s 128*50=6400 | pred 128*25=3200 | crp 128*30=3840
__device__ uint32_t g_im_hi[4608 * 64],  g_im_lo[4608 * 64];
__device__ uint32_t g_s_hi [6400 * 64],  g_s_lo [6400 * 64];
__device__ uint32_t g_pr_hi[3200 * 64],  g_pr_lo[3200 * 64];
__device__ uint32_t g_cr_hi[3840 * 64],  g_cr_lo[3840 * 64];

__device__ __forceinline__ float bf16_hi(float a) {
    uint16_t u;
    asm("cvt.rn.bf16.f32 %0, %1;" : "=h"(u) : "f"(a));
    return __uint_as_float(((uint32_t)u) << 16);
}
__device__ __forceinline__ uint32_t pack_bf16x2(float a, float b) {
    uint32_t r;
    asm("cvt.rn.bf16x2.f32 %0, %1, %2;" : "=r"(r) : "f"(b), "f"(a));
    return r;
}
__device__ __forceinline__ uint32_t smem_u32(const void* p) {
    uint32_t a;
    asm("{ .reg .u64 t; cvta.to.shared.u64 t, %1; cvt.u32.u64 %0, t; }"
        : "=r"(a) : "l"(p));
    return a;
}

// m16n8k16 bf16 MMA, fp32 accumulate (sm_80+ path; compiles for base sm_103)
#define MMA_BF16(d, a, b) \
    asm volatile("mma.sync.aligned.m16n8k16.row.col.f32.bf16.bf16.f32 " \
        "{%0,%1,%2,%3}, {%4,%5,%6,%7}, {%8,%9}, {%0,%1,%2,%3};" \
        : "+f"((d)[0]), "+f"((d)[1]), "+f"((d)[2]), "+f"((d)[3]) \
        : "r"((a)[0]), "r"((a)[1]), "r"((a)[2]), "r"((a)[3]), \
          "r"((b)[0]), "r"((b)[1]))

// ldmatrix x4: four 8x8 b16 matrices, one per 8-lane address group.
#define LDSM_X4(r0, r1, r2, r3, addr) \
    asm volatile("ldmatrix.sync.aligned.m8n8.x4.shared.b16 {%0,%1,%2,%3}, [%4];" \
        : "=r"(r0), "=r"(r1), "=r"(r2), "=r"(r3) : "r"(addr))

// ---- Preprocess: fp32 -> hi/lo bf16x2 planes, all 4 tensors in one kernel.
static constexpr int NQ_IM = 4608 * 32;   // float4 count
static constexpr int NQ_S  = 6400 * 32;
static constexpr int NQ_PR = 3200 * 32;
static constexpr int NQ_CR = 3840 * 32;
static constexpr int NQ_TOTAL = NQ_IM + NQ_S + NQ_PR + NQ_CR;   // 577536

__global__ __launch_bounds__(256)
void preprocess(const float* __restrict__ im, const float* __restrict__ s,
                const float* __restrict__ pr, const float* __restrict__ cr)
{
    int idx = blockIdx.x * 256 + threadIdx.x;
    if (idx >= NQ_TOTAL) return;
    const float4* src;
    uint2 *hi, *lo;
    int local = idx;
    if (idx < NQ_IM) {
        src = (const float4*)im; hi = (uint2*)g_im_hi; lo = (uint2*)g_im_lo;
    } else if (idx < NQ_IM + NQ_S) {
        local -= NQ_IM;
        src = (const float4*)s;  hi = (uint2*)g_s_hi;  lo = (uint2*)g_s_lo;
    } else if (idx < NQ_IM + NQ_S + NQ_PR) {
        local -= NQ_IM + NQ_S;
        src = (const float4*)pr; hi = (uint2*)g_pr_hi; lo = (uint2*)g_pr_lo;
    } else {
        local -= NQ_IM + NQ_S + NQ_PR;
        src = (const float4*)cr; hi = (uint2*)g_cr_hi; lo = (uint2*)g_cr_lo;
    }
    float4 v = src[local];
    float hx = bf16_hi(v.x), hy = bf16_hi(v.y);
    float hz = bf16_hi(v.z), hw = bf16_hi(v.w);
    uint2 hwd, lwd;
    hwd.x = (__float_as_uint(hy) & 0xFFFF0000u) | (__float_as_uint(hx) >> 16);
    hwd.y = (__float_as_uint(hw) & 0xFFFF0000u) | (__float_as_uint(hz) >> 16);
    lwd.x = pack_bf16x2(v.x - hx, v.y - hy);
    lwd.y = pack_bf16x2(v.z - hz, v.w - hw);
    hi[local] = hwd;
    lo[local] = lwd;
}

// ---- SMEM: K chunked by 64 (32 words/row). Row stride 36 words
// (36 mod 32 == 4): ldmatrix 8-row phases hit banks {0,4,...,28} -> conflict-free.
static constexpr int KC = 64;                       // K chunk (elements)
static constexpr int SW = 36;                       // row stride (words)
static constexpr int OFF_A_HI = 0;                  // 128*36*4 = 18432 B
static constexpr int OFF_A_LO = 18432;
static constexpr int OFF_B_HI = 36864;
static constexpr int OFF_B_LO = 55296;
static constexpr int SMEM_TOTAL = 73728;            // 72 KB -> 2 CTAs/SM
static constexpr int SD = 131;  // epilogue Dcol stride: odd -> conflict-free reads

// ---------------------------------------------------------------------------
// score_body<O, W, NIMG, NCAP, CSLOT, SLOT>  (device inline)
// CTA: M=128 rows = NIMG images x O objects (zero-padded),
//      N=128 cols = NCAP captions x CSLOT word slots (zero-padded).
// Operands pre-split to bf16 hi/lo planes; staging is pure uint4 copy.
// Fragments loaded via ldmatrix.x4 (12 LDSM per 16-k step vs 48 LDS.32).
// 3-pass bf16 split: D = Ahi*Bhi + Ahi*Blo + Alo*Bhi.
// ---------------------------------------------------------------------------
template<int O, int W, int NIMG, int NCAP, int CSLOT, int SLOT>
__device__ __forceinline__
void score_body(char* smem, int gi, int cg,
                const uint32_t* __restrict__ Ahi_g,
                const uint32_t* __restrict__ Alo_g,
                const uint32_t* __restrict__ Bhi_g,
                const uint32_t* __restrict__ Blo_g,
                const int* __restrict__ img_l,
                const int* __restrict__ cap_l,
                int B)
{
    uint32_t* Ah = reinterpret_cast<uint32_t*>(smem + OFF_A_HI);
    uint32_t* Al = reinterpret_cast<uint32_t*>(smem + OFF_A_LO);
    uint32_t* Bh = reinterpret_cast<uint32_t*>(smem + OFF_B_HI);
    uint32_t* Bl = reinterpret_cast<uint32_t*>(smem + OFF_B_LO);
    const uint32_t sbase = smem_u32(smem);

    const int tid  = threadIdx.x;
    const int wid  = tid >> 5;
    const int lane = tid & 31;

    const int ng = min(NIMG, B - gi * NIMG);
    const int arows = ng * O;
    const int gbase = gi * NIMG * O;            // global A row base

    const int wm = wid & 3, wn = wid >> 2;
    const int m0 = wm * 32, n0 = wn * 64;

    // ---- Per-lane ldmatrix address parts (byte offsets within a plane) ----
    const int mat = lane >> 3, lr = lane & 7;
    uint32_t aoff[2], boff[4];
    #pragma unroll
    for (int ms = 0; ms < 2; ms++)
        aoff[ms] = (uint32_t)(((m0 + ms * 16 + (mat & 1) * 8 + lr) * SW
                               + (mat >> 1) * 4) * 4);
    #pragma unroll
    for (int p = 0; p < 4; p++)
        boff[p] = (uint32_t)(((n0 + (2 * p + (mat >> 1)) * 8 + lr) * SW
                              + (mat & 1) * 4) * 4);

    float acc[2][8][4];
    #pragma unroll
    for (int ms = 0; ms < 2; ms++)
        #pragma unroll
        for (int ns = 0; ns < 8; ns++)
            #pragma unroll
            for (int j = 0; j < 4; j++) acc[ms][ns][j] = 0.0f;

    const uint4* Ahi4 = reinterpret_cast<const uint4*>(Ahi_g);
    const uint4* Alo4 = reinterpret_cast<const uint4*>(Alo_g);
    const uint4* Bhi4 = reinterpret_cast<const uint4*>(Bhi_g);
    const uint4* Blo4 = reinterpret_cast<const uint4*>(Blo_g);
    const uint4 zero4 = make_uint4(0u, 0u, 0u, 0u);

    #pragma unroll 1
    for (int chunk = 0; chunk < 2; chunk++) {
        __syncthreads();   // previous chunk consumed

        // ---- Stage A chunk: pure copy (row = 8 uint4 of 32 words) ----
        #pragma unroll
        for (int u = tid; u < 128 * 8; u += 256) {
            int r = u >> 3, q = u & 7;
            uint4 h = zero4, l = zero4;
            if (r < arows) {
                int gidx = (gbase + r) * 16 + chunk * 8 + q;
                h = Ahi4[gidx]; l = Alo4[gidx];
            }
            int wi = r * SW + q * 4;
            *reinterpret_cast<uint4*>(Ah + wi) = h;
            *reinterpret_cast<uint4*>(Al + wi) = l;
        }
        // ---- Stage B chunk: slot-padded copy ----
        #pragma unroll
        for (int u = tid; u < 128 * 8; u += 256) {
            int n = u >> 3, q = u & 7;
            int ci = n / CSLOT, w = n % CSLOT;
            uint4 h = zero4, l = zero4;
            if (w < W) {
                int gidx = ((cg * NCAP + ci) * W + w) * 16 + chunk * 8 + q;
                h = Bhi4[gidx]; l = Blo4[gidx];
            }
            int wi = n * SW + q * 4;
            *reinterpret_cast<uint4*>(Bh + wi) = h;
            *reinterpret_cast<uint4*>(Bl + wi) = l;
        }
        __syncthreads();

        // ---- 4 k-steps of 16 per chunk; fragments via ldmatrix ----
        #pragma unroll
        for (int kk = 0; kk < KC / 2; kk += 8) {
            const uint32_t kb = (uint32_t)(kk * 4);
            uint32_t ah[2][4], al[2][4], bh[8][2], bl[8][2];
            #pragma unroll
            for (int ms = 0; ms < 2; ms++) {
                LDSM_X4(ah[ms][0], ah[ms][1], ah[ms][2], ah[ms][3],
                        sbase + OFF_A_HI + aoff[ms] + kb);
                LDSM_X4(al[ms][0], al[ms][1], al[ms][2], al[ms][3],
                        sbase + OFF_A_LO + aoff[ms] + kb);
            }
            #pragma unroll
            for (int p = 0; p < 4; p++) {
                LDSM_X4(bh[2 * p][0], bh[2 * p][1], bh[2 * p + 1][0], bh[2 * p + 1][1],
                        sbase + OFF_B_HI + boff[p] + kb);
                LDSM_X4(bl[2 * p][0], bl[2 * p][1], bl[2 * p + 1][0], bl[2 * p + 1][1],
                        sbase + OFF_B_LO + boff[p] + kb);
            }
            #pragma unroll
            for (int ms = 0; ms < 2; ms++)
                #pragma unroll
                for (int ns = 0; ns < 8; ns++) {
                    MMA_BF16(acc[ms][ns], ah[ms], bh[ns]);
                    MMA_BF16(acc[ms][ns], ah[ms], bl[ns]);
                    MMA_BF16(acc[ms][ns], al[ms], bh[ns]);
                }
        }
    }
    __syncthreads();   // MMAs done; whole smem reusable

    // ---- D (regs) -> SMEM col-major [col][row], stride SD=131 ----
    const int gr = lane >> 2, tc = lane & 3;
    float* Dcol = reinterpret_cast<float*>(smem);           // 128*131*4 = 67072 B
    float* pooled = reinterpret_cast<float*>(smem + 67072); // NIMG*128 floats
    #pragma unroll
    for (int ms = 0; ms < 2; ms++) {
        int r = m0 + ms * 16 + gr;
        #pragma unroll
        for (int ns = 0; ns < 8; ns++) {
            int c = n0 + ns * 8 + 2 * tc;
            Dcol[c * SD + r]           = acc[ms][ns][0];
            Dcol[(c + 1) * SD + r]     = acc[ms][ns][1];
            Dcol[c * SD + r + 8]       = acc[ms][ns][2];
            Dcol[(c + 1) * SD + r + 8] = acc[ms][ns][3];
        }
    }
    __syncthreads();

    // ---- Masked max over objects per (image, col) ----
    for (int u = tid; u < NIMG * 128; u += 256) {
        int j = u >> 7, c = u & 127;
        int lim = (j < ng) ? img_l[gi * NIMG + j] : 0;
        float m = NEG_BIG;
        const float* col = Dcol + c * SD + j * O;
        for (int r = 0; r < lim; r++) m = fmaxf(m, col[r]);
        pooled[u] = m;
    }
    __syncthreads();

    // ---- Per-(image, caption) word sums -> global scores ----
    if (tid < NIMG * NCAP) {
        int j = tid / NCAP, ci = tid % NCAP;
        if (j < ng) {
            float s = 0.0f;
            #pragma unroll
            for (int w = 0; w < W; w++) s += pooled[j * 128 + ci * CSLOT + w];
            int i = gi * NIMG + j, c = cg * NCAP + ci;
            float r = s / (float)cap_l[c];
            if (SLOT == 0) g_s1[i * B + c] = r;
            else           g_s2[i * B + c] = r;
        }
    }
}

// Grid split: term1 = 64 x 43 = 2752 CTAs, term2 = 32 x 26 = 832 CTAs.
static constexpr int G1 = 64 * 43;
static constexpr int G2 = 32 * 26;

__global__ __launch_bounds__(256, 2)
void score_fused(const uint32_t* __restrict__ im_hi, const uint32_t* __restrict__ im_lo,
                 const uint32_t* __restrict__ s_hi,  const uint32_t* __restrict__ s_lo,
                 const uint32_t* __restrict__ pr_hi, const uint32_t* __restrict__ pr_lo,
                 const uint32_t* __restrict__ cr_hi, const uint32_t* __restrict__ cr_lo,
                 const int* __restrict__ im_l, const int* __restrict__ s_l,
                 const int* __restrict__ pr_l, const int* __restrict__ cr_l,
                 int B)
{
    extern __shared__ char smem[];
    const int bid = blockIdx.x;
    if (bid < G1) {
        score_body<36, 50, 3, 2, 64, 0>(smem, bid / 64, bid % 64,
                                        im_hi, im_lo, s_hi, s_lo, im_l, s_l, B);
    } else {
        const int b2 = bid - G1;
        score_body<25, 30, 5, 4, 32, 1>(smem, b2 / 32, b2 % 32,
                                        pr_hi, pr_lo, cr_hi, cr_lo, pr_l, cr_l, B);
    }
}

// ---------------------------------------------------------------------------
// Hinge loss over B x B total scores (g_s1 + g_s2), SMEM-staged.
// 1024 threads: 8 threads per row; deterministic fixed-order ops.
// ---------------------------------------------------------------------------
static constexpr int LS = 129;                     // S row stride (words)
static constexpr int LOSS_SMEM = 128 * LS * 4;     // 66048 B

__global__ __launch_bounds__(1024)
void loss_kernel(float* __restrict__ out, int B)
{
    extern __shared__ float S[];
    __shared__ float red[128];
    const int tid = threadIdx.x;

    for (int u = tid; u < 128 * 128; u += 1024) {
        int r = u >> 7, c = u & 127;
        S[r * LS + c] = g_s1[u] + g_s2[u];
    }
    __syncthreads();

    const int row  = tid >> 3;
    const int part = tid & 7;
    const float dt = S[row * LS + row];

    float m1 = 0.0f, m2 = 0.0f;
    #pragma unroll
    for (int i = 0; i < 16; i++) {
        int k = part + 8 * i;
        if (k != row) {
            m1 = fmaxf(m1, MARGIN + S[row * LS + k] - dt);
            m2 = fmaxf(m2, MARGIN + S[k * LS + row] - dt);
        }
    }
    #pragma unroll
    for (int s = 4; s > 0; s >>= 1) {
        m1 = fmaxf(m1, __shfl_down_sync(0xffffffffu, m1, s, 8));
        m2 = fmaxf(m2, __shfl_down_sync(0xffffffffu, m2, s, 8));
    }
    if (part == 0) red[row] = m1 + m2;
    __syncthreads();

    if (tid < 64) red[tid] += red[tid + 64];
    __syncthreads();
    if (tid < 32) {
        float v = red[tid] + red[tid + 32];
        #pragma unroll
        for (int s = 16; s > 0; s >>= 1)
            v += __shfl_down_sync(0xffffffffu, v, s);
        if (tid == 0) out[0] = v;
    }
}

// ---------------------------------------------------------------------------
// Inputs (metadata order):
//  0 im (B,36,128) f32 | 1 im_l (B) i32 | 2 s (B,50,128) f32 | 3 s_l (B) i32
//  4 pred (B,25,128)   | 5 pred_l       | 6/7 unused | 8 c_r_pred (B,30,128) | 9 c_r_l
// Output: scalar f32.
// ---------------------------------------------------------------------------
extern "C" void kernel_launch(void* const* d_in, const int* in_sizes, int n_in,
                              void* d_out, int out_size)
{
    const float* im     = (const float*)d_in[0];
    const int*   im_l   = (const int*)  d_in[1];
    const float* s      = (const float*)d_in[2];
    const int*   s_l    = (const int*)  d_in[3];
    const float* pred   = (const float*)d_in[4];
    const int*   pred_l = (const int*)  d_in[5];
    const float* crp    = (const float*)d_in[8];
    const int*   crl    = (const int*)  d_in[9];

    const int B = in_sizes[1];   // 128

    static uint32_t *p_im_hi = nullptr, *p_im_lo, *p_s_hi, *p_s_lo,
                    *p_pr_hi, *p_pr_lo, *p_cr_hi, *p_cr_lo;
    if (!p_im_hi) {
        cudaGetSymbolAddress((void**)&p_im_hi, g_im_hi);
        cudaGetSymbolAddress((void**)&p_im_lo, g_im_lo);
        cudaGetSymbolAddress((void**)&p_s_hi,  g_s_hi);
        cudaGetSymbolAddress((void**)&p_s_lo,  g_s_lo);
        cudaGetSymbolAddress((void**)&p_pr_hi, g_pr_hi);
        cudaGetSymbolAddress((void**)&p_pr_lo, g_pr_lo);
        cudaGetSymbolAddress((void**)&p_cr_hi, g_cr_hi);
        cudaGetSymbolAddress((void**)&p_cr_lo, g_cr_lo);
        cudaFuncSetAttribute(score_fused,
                             cudaFuncAttributeMaxDynamicSharedMemorySize, SMEM_TOTAL);
        cudaFuncSetAttribute(loss_kernel,
                             cudaFuncAttributeMaxDynamicSharedMemorySize, LOSS_SMEM);
    }

    preprocess<<<(NQ_TOTAL + 255) / 256, 256>>>(im, s, pred, crp);

    score_fused<<<G1 + G2, 256, SMEM_TOTAL>>>(
        p_im_hi, p_im_lo, p_s_hi, p_s_lo,
        p_pr_hi, p_pr_lo, p_cr_hi, p_cr_lo,
        im_l, s_l, pred_l, crl, B);

    loss_kernel<<<1, 1024, LOSS_SMEM>>>((float*)d_out, B);
}